// round 1
// baseline (speedup 1.0000x reference)
#include <cuda_runtime.h>

#define HH 512
#define WW 512
#define NB 16
#define HWSZ (HH * WW)

// Ping-pong scratch (static __device__ arrays: allocation-free per harness rules)
static __device__ float2 g_dispA[NB * HWSZ];
static __device__ float2 g_dispB[NB * HWSZ];
static __device__ float  g_ldA[NB * HWSZ];
static __device__ float  g_ldB[NB * HWSZ];

__device__ __constant__ float EPS = 0.0078125f;         // 2^-7
__device__ __constant__ float SC  = 512.0f / 511.0f;    // size/(size-1)

// ---------------------------------------------------------------------------
// Bilinear helpers (zeros padding, align_corners=False semantics from ref)
// ---------------------------------------------------------------------------
struct BilW {
    int x0, y0;
    float w00, w01, w10, w11;
};

__device__ __forceinline__ BilW bil_weights(float sx, float sy) {
    BilW b;
    float xf = floorf(sx), yf = floorf(sy);
    float wx = sx - xf, wy = sy - yf;
    b.x0 = (int)xf; b.y0 = (int)yf;
    float iwx = 1.0f - wx, iwy = 1.0f - wy;
    b.w00 = iwx * iwy; b.w01 = wx * iwy;
    b.w10 = iwx * wy;  b.w11 = wx * wy;
    return b;
}

__device__ __forceinline__ float2 gather2(const float2* __restrict__ s, const BilW& b) {
    float2 acc = make_float2(0.0f, 0.0f);
    int x1 = b.x0 + 1, y1 = b.y0 + 1;
    bool xv0 = (unsigned)b.x0 < (unsigned)WW;
    bool xv1 = (unsigned)x1   < (unsigned)WW;
    if ((unsigned)b.y0 < (unsigned)HH) {
        const float2* row = s + b.y0 * WW;
        if (xv0) { float2 v = row[b.x0]; acc.x += b.w00 * v.x; acc.y += b.w00 * v.y; }
        if (xv1) { float2 v = row[x1];   acc.x += b.w01 * v.x; acc.y += b.w01 * v.y; }
    }
    if ((unsigned)y1 < (unsigned)HH) {
        const float2* row = s + y1 * WW;
        if (xv0) { float2 v = row[b.x0]; acc.x += b.w10 * v.x; acc.y += b.w10 * v.y; }
        if (xv1) { float2 v = row[x1];   acc.x += b.w11 * v.x; acc.y += b.w11 * v.y; }
    }
    return acc;
}

__device__ __forceinline__ float gather1(const float* __restrict__ s, const BilW& b) {
    float acc = 0.0f;
    int x1 = b.x0 + 1, y1 = b.y0 + 1;
    bool xv0 = (unsigned)b.x0 < (unsigned)WW;
    bool xv1 = (unsigned)x1   < (unsigned)WW;
    if ((unsigned)b.y0 < (unsigned)HH) {
        const float* row = s + b.y0 * WW;
        if (xv0) acc += b.w00 * row[b.x0];
        if (xv1) acc += b.w01 * row[x1];
    }
    if ((unsigned)y1 < (unsigned)HH) {
        const float* row = s + y1 * WW;
        if (xv0) acc += b.w10 * row[b.x0];
        if (xv1) acc += b.w11 * row[x1];
    }
    return acc;
}

// ---------------------------------------------------------------------------
// Init: disp0 = eps*vel ; ldjac0 = -sum_{n=1..4} (-eps)^n tr(J^n)/n
// J from depthwise Sobel (cross-correlation) on replicate-padded vel.
// ---------------------------------------------------------------------------
__global__ __launch_bounds__(256)
void init_kernel(const float* __restrict__ vel) {
    int x = blockIdx.x * 32 + threadIdx.x;
    int y = blockIdx.y * 8 + threadIdx.y;
    int n = blockIdx.z;

    const float* v0 = vel + (size_t)n * 2 * HWSZ;
    const float* v1 = v0 + HWSZ;

    int ym = max(y - 1, 0), yp = min(y + 1, HH - 1);
    int xm = max(x - 1, 0), xp = min(x + 1, WW - 1);

    // channel 0 (y-velocity) 3x3
    float p00 = v0[ym * WW + xm], p01 = v0[ym * WW + x], p02 = v0[ym * WW + xp];
    float p10 = v0[y  * WW + xm], p11 = v0[y  * WW + x], p12 = v0[y  * WW + xp];
    float p20 = v0[yp * WW + xm], p21 = v0[yp * WW + x], p22 = v0[yp * WW + xp];
    // channel 1 (x-velocity) 3x3
    float q00 = v1[ym * WW + xm], q01 = v1[ym * WW + x], q02 = v1[ym * WW + xp];
    float q10 = v1[y  * WW + xm], q11 = v1[y  * WW + x], q12 = v1[y  * WW + xp];
    float q20 = v1[yp * WW + xm], q21 = v1[yp * WW + x], q22 = v1[yp * WW + xp];

    // J00 = d(v0)/dy, J01 = d(v0)/dx, J10 = d(v1)/dy, J11 = d(v1)/dx
    float J00 = 0.125f * ((p20 + 2.0f * p21 + p22) - (p00 + 2.0f * p01 + p02));
    float J01 = 0.125f * ((p02 + 2.0f * p12 + p22) - (p00 + 2.0f * p10 + p20));
    float J10 = 0.125f * ((q20 + 2.0f * q21 + q22) - (q00 + 2.0f * q01 + q02));
    float J11 = 0.125f * ((q02 + 2.0f * q12 + q22) - (q00 + 2.0f * q10 + q20));

    float t1 = J00 + J11;
    // J^2
    float A00 = J00 * J00 + J01 * J10;
    float A01 = J00 * J01 + J01 * J11;
    float A10 = J10 * J00 + J11 * J10;
    float A11 = J10 * J01 + J11 * J11;
    float t2 = A00 + A11;
    // J^3 = A*J
    float B00 = A00 * J00 + A01 * J10;
    float B01 = A00 * J01 + A01 * J11;
    float B10 = A10 * J00 + A11 * J10;
    float B11 = A10 * J01 + A11 * J11;
    float t3 = B00 + B11;
    // J^4 = B*J (traces only)
    float C00 = B00 * J00 + B01 * J10;
    float C11 = B10 * J01 + B11 * J11;
    float t4 = C00 + C11;

    float e1 = EPS, e2 = e1 * e1, e3 = e2 * e1, e4 = e2 * e2;
    float ld = e1 * t1 - e2 * t2 * 0.5f + e3 * t3 * (1.0f / 3.0f) - e4 * t4 * 0.25f;

    size_t idx = (size_t)n * HWSZ + y * WW + x;
    g_dispA[idx] = make_float2(EPS * p11, EPS * q11);
    g_ldA[idx] = ld;
}

// ---------------------------------------------------------------------------
// One fused squaring step:
//   disp_new = disp_old + bilerp(disp_old @ p+disp_old)
//   ld_new   = ld_old   + bilerp(ld_old   @ p+disp_new)
// ---------------------------------------------------------------------------
template <bool FINAL>
__global__ __launch_bounds__(256)
void step_kernel(int parity, float* __restrict__ outDisp, float* __restrict__ outLd) {
    const float2* __restrict__ dOld = parity ? g_dispB : g_dispA;
    const float*  __restrict__ lOld = parity ? g_ldB   : g_ldA;
    float2* __restrict__ dNew = parity ? g_dispA : g_dispB;
    float*  __restrict__ lNew = parity ? g_ldA   : g_ldB;

    int x = blockIdx.x * 32 + threadIdx.x;
    int y = blockIdx.y * 8 + threadIdx.y;
    int n = blockIdx.z;

    const float2* dn = dOld + (size_t)n * HWSZ;
    const float*  ln = lOld + (size_t)n * HWSZ;
    int p = y * WW + x;

    float2 d = dn[p];

    float sy = ((float)y + d.x) * SC - 0.5f;
    float sx = ((float)x + d.y) * SC - 0.5f;
    BilW b1 = bil_weights(sx, sy);
    float2 g = gather2(dn, b1);
    float2 dnw = make_float2(d.x + g.x, d.y + g.y);

    float sy2 = ((float)y + dnw.x) * SC - 0.5f;
    float sx2 = ((float)x + dnw.y) * SC - 0.5f;
    BilW b2 = bil_weights(sx2, sy2);
    float lnw = ln[p] + gather1(ln, b2);

    if (FINAL) {
        float* od = outDisp + (size_t)n * 2 * HWSZ;
        od[p] = dnw.x;
        od[HWSZ + p] = dnw.y;
        outLd[(size_t)n * HWSZ + p] = lnw;
    } else {
        dNew[(size_t)n * HWSZ + p] = dnw;
        lNew[(size_t)n * HWSZ + p] = lnw;
    }
}

// ---------------------------------------------------------------------------
extern "C" void kernel_launch(void* const* d_in, const int* in_sizes, int n_in,
                              void* d_out, int out_size) {
    const float* vel = (const float*)d_in[0];
    float* out = (float*)d_out;
    float* outDisp = out;                                  // [16,2,512,512]
    float* outLd = out + (size_t)NB * 2 * HWSZ;            // [16,1,512,512]

    dim3 block(32, 8, 1);
    dim3 grid(WW / 32, HH / 8, NB);

    init_kernel<<<grid, block>>>(vel);
    // 7 squaring steps; steps 0..5 ping-pong, step 6 writes planar output
    step_kernel<false><<<grid, block>>>(0, nullptr, nullptr);  // A -> B
    step_kernel<false><<<grid, block>>>(1, nullptr, nullptr);  // B -> A
    step_kernel<false><<<grid, block>>>(0, nullptr, nullptr);  // A -> B
    step_kernel<false><<<grid, block>>>(1, nullptr, nullptr);  // B -> A
    step_kernel<false><<<grid, block>>>(0, nullptr, nullptr);  // A -> B
    step_kernel<false><<<grid, block>>>(1, nullptr, nullptr);  // B -> A
    step_kernel<true><<<grid, block>>>(0, outDisp, outLd);     // A -> out
}

// round 2
// speedup vs baseline: 1.2079x; 1.2079x over previous
#include <cuda_runtime.h>

#define HH 512
#define WW 512
#define NB 16
#define HWSZ (HH * WW)

static __device__ float2 g_dispA[NB * HWSZ];
static __device__ float2 g_dispB[NB * HWSZ];
static __device__ float  g_ldA[NB * HWSZ];
static __device__ float  g_ldB[NB * HWSZ];

#define EPS 0.0078125f           // 2^-7
#define SC  (512.0f / 511.0f)    // size/(size-1)

// ---------------------------------------------------------------------------
// Branchless bilinear weights: out-of-bounds taps get weight 0 (zeros padding),
// indices are clamped so the loads are always safe and unconditional.
// ---------------------------------------------------------------------------
struct BilT {
    int i00, i01, i10, i11;          // clamped flat offsets
    float w00, w01, w10, w11;        // masked weights
};

__device__ __forceinline__ BilT bil_taps(float sx, float sy) {
    float xf = floorf(sx), yf = floorf(sy);
    float wx = sx - xf, wy = sy - yf;
    int x0 = (int)xf, y0 = (int)yf;
    int x1 = x0 + 1,  y1 = y0 + 1;

    bool xv0 = (unsigned)x0 < (unsigned)WW;
    bool xv1 = (unsigned)x1 < (unsigned)WW;
    bool yv0 = (unsigned)y0 < (unsigned)HH;
    bool yv1 = (unsigned)y1 < (unsigned)HH;

    int xc0 = min(max(x0, 0), WW - 1);
    int xc1 = min(max(x1, 0), WW - 1);
    int yc0 = min(max(y0, 0), HH - 1);
    int yc1 = min(max(y1, 0), HH - 1);

    float iwx = 1.0f - wx, iwy = 1.0f - wy;
    BilT t;
    t.w00 = (xv0 && yv0) ? iwx * iwy : 0.0f;
    t.w01 = (xv1 && yv0) ? wx  * iwy : 0.0f;
    t.w10 = (xv0 && yv1) ? iwx * wy  : 0.0f;
    t.w11 = (xv1 && yv1) ? wx  * wy  : 0.0f;
    t.i00 = yc0 * WW + xc0;
    t.i01 = yc0 * WW + xc1;
    t.i10 = yc1 * WW + xc0;
    t.i11 = yc1 * WW + xc1;
    return t;
}

__device__ __forceinline__ float2 gather2(const float2* __restrict__ s, const BilT& t) {
    float2 v00 = s[t.i00];
    float2 v01 = s[t.i01];
    float2 v10 = s[t.i10];
    float2 v11 = s[t.i11];
    float2 acc;
    acc.x = t.w00 * v00.x + t.w01 * v01.x + t.w10 * v10.x + t.w11 * v11.x;
    acc.y = t.w00 * v00.y + t.w01 * v01.y + t.w10 * v10.y + t.w11 * v11.y;
    return acc;
}

__device__ __forceinline__ float gather1(const float* __restrict__ s, const BilT& t) {
    float v00 = s[t.i00];
    float v01 = s[t.i01];
    float v10 = s[t.i10];
    float v11 = s[t.i11];
    return t.w00 * v00 + t.w01 * v01 + t.w10 * v10 + t.w11 * v11;
}

// ---------------------------------------------------------------------------
// Init: disp0 = eps*vel ; ldjac0 = -sum_{n=1..4} (-eps)^n tr(J^n)/n
// ---------------------------------------------------------------------------
__global__ __launch_bounds__(256)
void init_kernel(const float* __restrict__ vel) {
    int x = blockIdx.x * 32 + threadIdx.x;
    int y = blockIdx.y * 8 + threadIdx.y;
    int n = blockIdx.z;

    const float* v0 = vel + (size_t)n * 2 * HWSZ;
    const float* v1 = v0 + HWSZ;

    int ym = max(y - 1, 0), yp = min(y + 1, HH - 1);
    int xm = max(x - 1, 0), xp = min(x + 1, WW - 1);

    float p00 = v0[ym * WW + xm], p01 = v0[ym * WW + x], p02 = v0[ym * WW + xp];
    float p10 = v0[y  * WW + xm], p11 = v0[y  * WW + x], p12 = v0[y  * WW + xp];
    float p20 = v0[yp * WW + xm], p21 = v0[yp * WW + x], p22 = v0[yp * WW + xp];
    float q00 = v1[ym * WW + xm], q01 = v1[ym * WW + x], q02 = v1[ym * WW + xp];
    float q10 = v1[y  * WW + xm], q11 = v1[y  * WW + x], q12 = v1[y  * WW + xp];
    float q20 = v1[yp * WW + xm], q21 = v1[yp * WW + x], q22 = v1[yp * WW + xp];

    float J00 = 0.125f * ((p20 + 2.0f * p21 + p22) - (p00 + 2.0f * p01 + p02));
    float J01 = 0.125f * ((p02 + 2.0f * p12 + p22) - (p00 + 2.0f * p10 + p20));
    float J10 = 0.125f * ((q20 + 2.0f * q21 + q22) - (q00 + 2.0f * q01 + q02));
    float J11 = 0.125f * ((q02 + 2.0f * q12 + q22) - (q00 + 2.0f * q10 + q20));

    float t1 = J00 + J11;
    float A00 = J00 * J00 + J01 * J10;
    float A01 = J00 * J01 + J01 * J11;
    float A10 = J10 * J00 + J11 * J10;
    float A11 = J10 * J01 + J11 * J11;
    float t2 = A00 + A11;
    float B00 = A00 * J00 + A01 * J10;
    float B01 = A00 * J01 + A01 * J11;
    float B10 = A10 * J00 + A11 * J10;
    float B11 = A10 * J01 + A11 * J11;
    float t3 = B00 + B11;
    float C00 = B00 * J00 + B01 * J10;
    float C11 = B10 * J01 + B11 * J11;
    float t4 = C00 + C11;

    float e1 = EPS, e2 = e1 * e1, e3 = e2 * e1, e4 = e2 * e2;
    float ld = e1 * t1 - e2 * t2 * 0.5f + e3 * t3 * (1.0f / 3.0f) - e4 * t4 * 0.25f;

    size_t idx = (size_t)n * HWSZ + y * WW + x;
    g_dispA[idx] = make_float2(EPS * p11, EPS * q11);
    g_ldA[idx] = ld;
}

// ---------------------------------------------------------------------------
// One fused squaring step, 2 pixels per thread (x and x+32) for ILP.
//   disp_new = disp_old + bilerp(disp_old @ p+disp_old)
//   ld_new   = ld_old   + bilerp(ld_old   @ p+disp_new)
// ---------------------------------------------------------------------------
template <bool FINAL>
__global__ __launch_bounds__(256)
void step_kernel(int parity, float* __restrict__ outDisp, float* __restrict__ outLd) {
    const float2* __restrict__ dOld = parity ? g_dispB : g_dispA;
    const float*  __restrict__ lOld = parity ? g_ldB   : g_ldA;
    float2* __restrict__ dNew = parity ? g_dispA : g_dispB;
    float*  __restrict__ lNew = parity ? g_ldA   : g_ldB;

    int xa = blockIdx.x * 64 + threadIdx.x;   // first pixel
    int xb = xa + 32;                         // second pixel (warp-contiguous group)
    int y  = blockIdx.y * 8 + threadIdx.y;
    int n  = blockIdx.z;

    const float2* dn = dOld + (size_t)n * HWSZ;
    const float*  ln = lOld + (size_t)n * HWSZ;
    int pa = y * WW + xa;
    int pb = y * WW + xb;

    // round 0: center loads (independent)
    float2 da = dn[pa];
    float2 db = dn[pb];
    float  la = ln[pa];
    float  lb = ln[pb];

    // round 1: disp self-gather, both pixels in flight together
    BilT ta1 = bil_taps(((float)xa + da.y) * SC - 0.5f, ((float)y + da.x) * SC - 0.5f);
    BilT tb1 = bil_taps(((float)xb + db.y) * SC - 0.5f, ((float)y + db.x) * SC - 0.5f);
    float2 ga = gather2(dn, ta1);
    float2 gb = gather2(dn, tb1);
    float2 dna = make_float2(da.x + ga.x, da.y + ga.y);
    float2 dnb = make_float2(db.x + gb.x, db.y + gb.y);

    // round 2: ldjac gather at the NEW displacement, both pixels in flight
    BilT ta2 = bil_taps(((float)xa + dna.y) * SC - 0.5f, ((float)y + dna.x) * SC - 0.5f);
    BilT tb2 = bil_taps(((float)xb + dnb.y) * SC - 0.5f, ((float)y + dnb.x) * SC - 0.5f);
    float lna = la + gather1(ln, ta2);
    float lnb = lb + gather1(ln, tb2);

    if (FINAL) {
        float* od = outDisp + (size_t)n * 2 * HWSZ;
        od[pa] = dna.x;  od[pb] = dnb.x;
        od[HWSZ + pa] = dna.y;  od[HWSZ + pb] = dnb.y;
        float* ol = outLd + (size_t)n * HWSZ;
        ol[pa] = lna;  ol[pb] = lnb;
    } else {
        float2* dd = dNew + (size_t)n * HWSZ;
        dd[pa] = dna;  dd[pb] = dnb;
        float* ll = lNew + (size_t)n * HWSZ;
        ll[pa] = lna;  ll[pb] = lnb;
    }
}

// ---------------------------------------------------------------------------
extern "C" void kernel_launch(void* const* d_in, const int* in_sizes, int n_in,
                              void* d_out, int out_size) {
    const float* vel = (const float*)d_in[0];
    float* out = (float*)d_out;
    float* outDisp = out;                          // [16,2,512,512]
    float* outLd = out + (size_t)NB * 2 * HWSZ;    // [16,1,512,512]

    dim3 blockI(32, 8, 1);
    dim3 gridI(WW / 32, HH / 8, NB);
    init_kernel<<<gridI, blockI>>>(vel);

    dim3 blockS(32, 8, 1);
    dim3 gridS(WW / 64, HH / 8, NB);
    step_kernel<false><<<gridS, blockS>>>(0, nullptr, nullptr);  // A -> B
    step_kernel<false><<<gridS, blockS>>>(1, nullptr, nullptr);  // B -> A
    step_kernel<false><<<gridS, blockS>>>(0, nullptr, nullptr);  // A -> B
    step_kernel<false><<<gridS, blockS>>>(1, nullptr, nullptr);  // B -> A
    step_kernel<false><<<gridS, blockS>>>(0, nullptr, nullptr);  // A -> B
    step_kernel<false><<<gridS, blockS>>>(1, nullptr, nullptr);  // B -> A
    step_kernel<true><<<gridS, blockS>>>(0, outDisp, outLd);     // A -> out
}

// round 3
// speedup vs baseline: 1.4181x; 1.1740x over previous
#include <cuda_runtime.h>

#define HH 512
#define WW 512
#define NB 16
#define HWSZ (HH * WW)

// Padded scratch layout: 4-px apron of zeros on every side.
#define PAD 4
#define PW  (WW + 2 * PAD)     // 520
#define PH  (HH + 2 * PAD)     // 520
#define PHW (PW * PH)          // 270400

static __device__ float2 g_dispA[NB * PHW];
static __device__ float2 g_dispB[NB * PHW];
static __device__ float  g_ldA[NB * PHW];
static __device__ float  g_ldB[NB * PHW];

#define EPS 0.0078125f           // 2^-7
#define SC  (512.0f / 511.0f)    // size/(size-1)

// ---------------------------------------------------------------------------
// Apron-based bilinear taps: clamp float coords into the apron-safe range,
// then load unconditionally. Out-of-image taps read stored zeros.
// ---------------------------------------------------------------------------
struct BilT {
    int base;                        // flat padded offset of (y0, x0)
    float w00, w01, w10, w11;
};

__device__ __forceinline__ BilT bil_taps(float sx, float sy) {
    sx = fminf(fmaxf(sx, -3.0f), 514.0f);
    sy = fminf(fmaxf(sy, -3.0f), 514.0f);
    float xf = floorf(sx), yf = floorf(sy);
    float wx = sx - xf,  wy = sy - yf;
    int x0 = (int)xf, y0 = (int)yf;

    float iwx = 1.0f - wx, iwy = 1.0f - wy;
    BilT t;
    t.w00 = iwx * iwy;
    t.w01 = wx  * iwy;
    t.w10 = iwx * wy;
    t.w11 = wx  * wy;
    t.base = (y0 + PAD) * PW + (x0 + PAD);
    return t;
}

__device__ __forceinline__ float2 gather2(const float2* __restrict__ s, const BilT& t) {
    const float2* p = s + t.base;
    float2 v00 = p[0];
    float2 v01 = p[1];
    float2 v10 = p[PW];
    float2 v11 = p[PW + 1];
    float2 acc;
    acc.x = t.w00 * v00.x + t.w01 * v01.x + t.w10 * v10.x + t.w11 * v11.x;
    acc.y = t.w00 * v00.y + t.w01 * v01.y + t.w10 * v10.y + t.w11 * v11.y;
    return acc;
}

__device__ __forceinline__ float gather1(const float* __restrict__ s, const BilT& t) {
    const float* p = s + t.base;
    return t.w00 * p[0] + t.w01 * p[1] + t.w10 * p[PW] + t.w11 * p[PW + 1];
}

// ---------------------------------------------------------------------------
// Init over the PADDED grid:
//   interior: disp0 = eps*vel ; ldjac0 = -sum_{n=1..4} (-eps)^n tr(J^n)/n
//   apron:    write zeros to ALL four scratch buffers (steps never touch apron,
//             so it stays zero for every subsequent gather).
// ---------------------------------------------------------------------------
__global__ __launch_bounds__(256)
void init_kernel(const float* __restrict__ vel) {
    int px = blockIdx.x * 32 + threadIdx.x;   // padded coords
    int py = blockIdx.y * 8 + threadIdx.y;
    int n  = blockIdx.z;
    if (px >= PW || py >= PH) return;

    size_t pidx = (size_t)n * PHW + py * PW + px;
    int x = px - PAD, y = py - PAD;

    bool interior = ((unsigned)x < (unsigned)WW) && ((unsigned)y < (unsigned)HH);
    if (!interior) {
        g_dispA[pidx] = make_float2(0.0f, 0.0f);
        g_dispB[pidx] = make_float2(0.0f, 0.0f);
        g_ldA[pidx] = 0.0f;
        g_ldB[pidx] = 0.0f;
        return;
    }

    const float* v0 = vel + (size_t)n * 2 * HWSZ;
    const float* v1 = v0 + HWSZ;

    int ym = max(y - 1, 0), yp = min(y + 1, HH - 1);
    int xm = max(x - 1, 0), xp = min(x + 1, WW - 1);

    float p00 = v0[ym * WW + xm], p01 = v0[ym * WW + x], p02 = v0[ym * WW + xp];
    float p10 = v0[y  * WW + xm], p11 = v0[y  * WW + x], p12 = v0[y  * WW + xp];
    float p20 = v0[yp * WW + xm], p21 = v0[yp * WW + x], p22 = v0[yp * WW + xp];
    float q00 = v1[ym * WW + xm], q01 = v1[ym * WW + x], q02 = v1[ym * WW + xp];
    float q10 = v1[y  * WW + xm], q11 = v1[y  * WW + x], q12 = v1[y  * WW + xp];
    float q20 = v1[yp * WW + xm], q21 = v1[yp * WW + x], q22 = v1[yp * WW + xp];

    float J00 = 0.125f * ((p20 + 2.0f * p21 + p22) - (p00 + 2.0f * p01 + p02));
    float J01 = 0.125f * ((p02 + 2.0f * p12 + p22) - (p00 + 2.0f * p10 + p20));
    float J10 = 0.125f * ((q20 + 2.0f * q21 + q22) - (q00 + 2.0f * q01 + q02));
    float J11 = 0.125f * ((q02 + 2.0f * q12 + q22) - (q00 + 2.0f * q10 + q20));

    float t1 = J00 + J11;
    float A00 = J00 * J00 + J01 * J10;
    float A01 = J00 * J01 + J01 * J11;
    float A10 = J10 * J00 + J11 * J10;
    float A11 = J10 * J01 + J11 * J11;
    float t2 = A00 + A11;
    float B00 = A00 * J00 + A01 * J10;
    float B01 = A00 * J01 + A01 * J11;
    float B10 = A10 * J00 + A11 * J10;
    float B11 = A10 * J01 + A11 * J11;
    float t3 = B00 + B11;
    float C00 = B00 * J00 + B01 * J10;
    float C11 = B10 * J01 + B11 * J11;
    float t4 = C00 + C11;

    float e1 = EPS, e2 = e1 * e1, e3 = e2 * e1, e4 = e2 * e2;
    float ld = e1 * t1 - e2 * t2 * 0.5f + e3 * t3 * (1.0f / 3.0f) - e4 * t4 * 0.25f;

    g_dispA[pidx] = make_float2(EPS * p11, EPS * q11);
    g_ldA[pidx] = ld;
}

// ---------------------------------------------------------------------------
// One fused squaring step, 2 pixels per thread (x and x+32).
//   disp_new = disp_old + bilerp(disp_old @ p+disp_old)
//   ld_new   = ld_old   + bilerp(ld_old   @ p+disp_new)
// ---------------------------------------------------------------------------
template <bool FINAL>
__global__ __launch_bounds__(256)
void step_kernel(int parity, float* __restrict__ outDisp, float* __restrict__ outLd) {
    const float2* __restrict__ dOld = parity ? g_dispB : g_dispA;
    const float*  __restrict__ lOld = parity ? g_ldB   : g_ldA;
    float2* __restrict__ dNew = parity ? g_dispA : g_dispB;
    float*  __restrict__ lNew = parity ? g_ldA   : g_ldB;

    int xa = blockIdx.x * 64 + threadIdx.x;
    int xb = xa + 32;
    int y  = blockIdx.y * 8 + threadIdx.y;
    int n  = blockIdx.z;

    const float2* dn = dOld + (size_t)n * PHW;
    const float*  ln = lOld + (size_t)n * PHW;
    int pa = (y + PAD) * PW + (xa + PAD);
    int pb = pa + 32;

    // round 0: center loads
    float2 da = dn[pa];
    float2 db = dn[pb];
    float  la = ln[pa];
    float  lb = ln[pb];

    // round 1: disp self-gather, both pixels in flight
    BilT ta1 = bil_taps(((float)xa + da.y) * SC - 0.5f, ((float)y + da.x) * SC - 0.5f);
    BilT tb1 = bil_taps(((float)xb + db.y) * SC - 0.5f, ((float)y + db.x) * SC - 0.5f);
    float2 ga = gather2(dn, ta1);
    float2 gb = gather2(dn, tb1);
    float2 dna = make_float2(da.x + ga.x, da.y + ga.y);
    float2 dnb = make_float2(db.x + gb.x, db.y + gb.y);

    // round 2: ldjac gather at the NEW displacement
    BilT ta2 = bil_taps(((float)xa + dna.y) * SC - 0.5f, ((float)y + dna.x) * SC - 0.5f);
    BilT tb2 = bil_taps(((float)xb + dnb.y) * SC - 0.5f, ((float)y + dnb.x) * SC - 0.5f);
    float lna = la + gather1(ln, ta2);
    float lnb = lb + gather1(ln, tb2);

    if (FINAL) {
        int qa = y * WW + xa;
        int qb = qa + 32;
        float* od = outDisp + (size_t)n * 2 * HWSZ;
        od[qa] = dna.x;  od[qb] = dnb.x;
        od[HWSZ + qa] = dna.y;  od[HWSZ + qb] = dnb.y;
        float* ol = outLd + (size_t)n * HWSZ;
        ol[qa] = lna;  ol[qb] = lnb;
    } else {
        float2* dd = dNew + (size_t)n * PHW;
        dd[pa] = dna;  dd[pb] = dnb;
        float* ll = lNew + (size_t)n * PHW;
        ll[pa] = lna;  ll[pb] = lnb;
    }
}

// ---------------------------------------------------------------------------
extern "C" void kernel_launch(void* const* d_in, const int* in_sizes, int n_in,
                              void* d_out, int out_size) {
    const float* vel = (const float*)d_in[0];
    float* out = (float*)d_out;
    float* outDisp = out;                          // [16,2,512,512]
    float* outLd = out + (size_t)NB * 2 * HWSZ;    // [16,1,512,512]

    dim3 blockI(32, 8, 1);
    dim3 gridI((PW + 31) / 32, (PH + 7) / 8, NB);  // covers padded grid incl. apron
    init_kernel<<<gridI, blockI>>>(vel);

    dim3 blockS(32, 8, 1);
    dim3 gridS(WW / 64, HH / 8, NB);
    step_kernel<false><<<gridS, blockS>>>(0, nullptr, nullptr);  // A -> B
    step_kernel<false><<<gridS, blockS>>>(1, nullptr, nullptr);  // B -> A
    step_kernel<false><<<gridS, blockS>>>(0, nullptr, nullptr);  // A -> B
    step_kernel<false><<<gridS, blockS>>>(1, nullptr, nullptr);  // B -> A
    step_kernel<false><<<gridS, blockS>>>(0, nullptr, nullptr);  // A -> B
    step_kernel<false><<<gridS, blockS>>>(1, nullptr, nullptr);  // B -> A
    step_kernel<true><<<gridS, blockS>>>(0, outDisp, outLd);     // A -> out
}